// round 15
// baseline (speedup 1.0000x reference)
#include <cuda_runtime.h>
#include <cuda_fp16.h>
#include <stdint.h>
#include <math.h>

// ---------------- problem constants ----------------
#define CDIM   1024
#define NTOK   16384             // B*T = 4*4096
#define C3     (3 * CDIM)        // 3072

// ---------------- scratch (allocation-free rule) ----------------
__device__ __half g_qkvh[(size_t)NTOK * C3];    // fp16 qkv
__device__ __half g_yh [(size_t)NTOK * CDIM];   // fp16 y
__device__ __half g_xh [(size_t)NTOK * CDIM];
__device__ __half g_w1h[(size_t)C3 * CDIM];
__device__ __half g_w2h[(size_t)CDIM * CDIM];

// ---------------- PTX helpers (baseline sm_80+ only) ----------------
__device__ __forceinline__ uint32_t smem_u32(const void* p) {
    uint32_t a;
    asm("{ .reg .u64 t; cvta.to.shared.u64 t, %1; cvt.u32.u64 %0, t; }"
        : "=r"(a) : "l"(p));
    return a;
}

#define CP_ASYNC16(dst_u32, src_ptr) \
    asm volatile("cp.async.cg.shared.global [%0], [%1], 16;" \
                 :: "r"(dst_u32), "l"(src_ptr) : "memory")
#define CP_COMMIT() asm volatile("cp.async.commit_group;" ::: "memory")
#define CP_WAIT(n)  asm volatile("cp.async.wait_group %0;" :: "n"(n) : "memory")

#define LDSM4(r, addr) \
    asm volatile("ldmatrix.sync.aligned.m8n8.x4.shared.b16 {%0,%1,%2,%3}, [%4];" \
        : "=r"((r)[0]), "=r"((r)[1]), "=r"((r)[2]), "=r"((r)[3]) : "r"(addr))

// single-pass fp16 m16n8k16, fp32 accumulate
#define MMA_F16(d, a, b0, b1) \
    asm volatile("mma.sync.aligned.m16n8k16.row.col.f32.f16.f16.f32 " \
        "{%0,%1,%2,%3}, {%4,%5,%6,%7}, {%8,%9}, {%0,%1,%2,%3};" \
        : "+f"((d)[0]), "+f"((d)[1]), "+f"((d)[2]), "+f"((d)[3]) \
        : "r"((a)[0]), "r"((a)[1]), "r"((a)[2]), "r"((a)[3]), "r"(b0), "r"(b1))

// ---------------- smem geometry (XOR swizzle, 128 B rows) ----------------
#define PITCH   128
#define TILE_B  (128 * PITCH)      // 16384 B
#define OFF_B   TILE_B
#define STAGE_B (2 * TILE_B)       // 32768 B
#define NSTG    3
#define SMEM_B  (NSTG * STAGE_B)   // 98304 B -> 2 CTAs/SM
#define BKC     64                 // K halves per chunk (4 k16 steps)
#define KFIX    1024               // compile-time K (both GEMMs)
#define KC      (KFIX / BKC)       // 16 chunks, fully unrolled

// ---------------------------------------------------------------------------
// C = A[M,K] @ B[N,K]^T (+bias); A,B fp16, fp32 accum. K = 1024 compile-time.
// OUT_HALF selects fp16 (Ch) vs fp32 (C) output at compile time.
// 128x128 CTA tile, 8 warps (64x32), cp.async pipeline with CROSS-CHUNK
// fragment preload: chunk c+1's step-0 ldmatrix woven into chunk c's step-3
// MMA block, so no post-barrier LDSM convoy. Protocol per iter c:
//   [c, c+1 resident]  issue(c+2); MMA steps 0..3 (weaving next frags);
//   CP_WAIT(0); __syncthreads();
// ---------------------------------------------------------------------------
template <bool OUT_HALF>
__global__ __launch_bounds__(256, 2) void f16_gemm(
    const __half* __restrict__ A, const __half* __restrict__ B,
    const float* __restrict__ bias, float* __restrict__ C,
    __half* __restrict__ Ch, int M, int N)
{
    extern __shared__ char sm[];
    const uint32_t sbase = smem_u32(sm);

    const int tid  = threadIdx.x;
    const int lane = tid & 31;
    const int wid  = tid >> 5;
    const int wm   = wid & 1;       // M half
    const int wn   = wid >> 1;      // N quarter
    const int bm   = blockIdx.y * 128;
    const int bn   = blockIdx.x * 128;

    // ---- loader: 128 rows x 8 chunks; thread -> (row tid>>1, chunk-quad tid&1) ----
    const int lr = tid >> 1;
    const int lh = tid & 1;
    const __half* gA = A + (size_t)(bm + lr) * KFIX + lh * 32;
    const __half* gB = B + (size_t)(bn + lr) * KFIX + lh * 32;
    uint32_t sw[4];
    #pragma unroll
    for (int j = 0; j < 4; j++) sw[j] = (uint32_t)(((lh * 4 + j) ^ (lr & 7)) << 4);
    const uint32_t sRowBase = (uint32_t)(lr * PITCH);

    // ---- ldmatrix lane addressing ----
    const int l8 = lane & 7;
    const int cg = lane >> 4;            // 16B chunk group (0/1) within k16
    const uint32_t aRow = (uint32_t)((wm * 64 + (lane & 15)) * PITCH);
    const uint32_t bRow = (uint32_t)((wn * 32 + (lane & 15)) * PITCH);
    uint32_t kSw[4];                     // swizzled chunk offset per k16-step
    #pragma unroll
    for (int s = 0; s < 4; s++)
        kSw[s] = (uint32_t)(((s * 2 + cg) ^ l8) << 4);

    float acc[4][4][4];
    #pragma unroll
    for (int i = 0; i < 4; i++)
        #pragma unroll
        for (int j = 0; j < 4; j++)
            #pragma unroll
            for (int q = 0; q < 4; q++) acc[i][j][q] = 0.0f;

    auto issue = [&](int stg, int ko) {
        const uint32_t dA = sbase + (uint32_t)stg * STAGE_B + sRowBase;
        const uint32_t dB = dA + OFF_B;
        const __half* sa = gA + ko;
        const __half* sb = gB + ko;
        #pragma unroll
        for (int j = 0; j < 4; j++) {
            CP_ASYNC16(dA + sw[j], sa + j * 8);
            CP_ASYNC16(dB + sw[j], sb + j * 8);
        }
    };

    // prologue: chunks 0 and 1 resident before loop
    issue(0, 0);   CP_COMMIT();
    issue(1, BKC); CP_COMMIT();
    CP_WAIT(0);
    __syncthreads();

    uint32_t ah[2][4][4], bh[2][2][4];

    // preload step-0 frags of chunk 0 (stage 0)
    {
        const uint32_t aB = sbase + aRow;
        const uint32_t bB = sbase + OFF_B + bRow;
        #pragma unroll
        for (int i = 0; i < 4; i++) LDSM4(ah[0][i], aB + kSw[0] + (uint32_t)(i * 16 * PITCH));
        #pragma unroll
        for (int p = 0; p < 2; p++) LDSM4(bh[0][p], bB + kSw[0] + (uint32_t)(p * 16 * PITCH));
    }

    #pragma unroll
    for (int c = 0; c < KC; c++) {
        // issue chunk c+2 into stage (c+2)%3 (its readers finished in iter c-1)
        if (c + 2 < KC) { issue((c + 2) % NSTG, (c + 2) * BKC); CP_COMMIT(); }

        const uint32_t base_c = sbase + (uint32_t)((c % NSTG) * STAGE_B);
        const uint32_t aB  = base_c + aRow;
        const uint32_t bB  = base_c + OFF_B + bRow;
        const uint32_t base_n = sbase + (uint32_t)(((c + 1) % NSTG) * STAGE_B);
        const uint32_t aBn = base_n + aRow;
        const uint32_t bBn = base_n + OFF_B + bRow;

        #pragma unroll
        for (int s = 0; s < 4; s++) {
            const int cur = s & 1;
            const int nxt = cur ^ 1;
            #pragma unroll
            for (int m = 0; m < 16; m++) {
                const int i = m >> 2, j = m & 3;
                const int nb = j >> 1, jj = j & 1;
                const uint32_t b0 = jj ? bh[cur][nb][1] : bh[cur][nb][0];
                const uint32_t b1 = jj ? bh[cur][nb][3] : bh[cur][nb][2];
                MMA_F16(acc[i][j], ah[cur][i], b0, b1);
                if (s < 3) {
                    // weave this chunk's next k16-step frags
                    if (m == 2)
                        LDSM4(ah[nxt][0], aB + kSw[s + 1] + (uint32_t)(0 * 16 * PITCH));
                    if (m == 4)
                        LDSM4(ah[nxt][1], aB + kSw[s + 1] + (uint32_t)(1 * 16 * PITCH));
                    if (m == 6)
                        LDSM4(ah[nxt][2], aB + kSw[s + 1] + (uint32_t)(2 * 16 * PITCH));
                    if (m == 8)
                        LDSM4(ah[nxt][3], aB + kSw[s + 1] + (uint32_t)(3 * 16 * PITCH));
                    if (m == 10)
                        LDSM4(bh[nxt][0], bB + kSw[s + 1] + (uint32_t)(0 * 16 * PITCH));
                    if (m == 12)
                        LDSM4(bh[nxt][1], bB + kSw[s + 1] + (uint32_t)(1 * 16 * PITCH));
                } else if (c + 1 < KC) {
                    // weave NEXT chunk's step-0 frags (stage c+1 resident by invariant)
                    if (m == 2)
                        LDSM4(ah[nxt][0], aBn + kSw[0] + (uint32_t)(0 * 16 * PITCH));
                    if (m == 4)
                        LDSM4(ah[nxt][1], aBn + kSw[0] + (uint32_t)(1 * 16 * PITCH));
                    if (m == 6)
                        LDSM4(ah[nxt][2], aBn + kSw[0] + (uint32_t)(2 * 16 * PITCH));
                    if (m == 8)
                        LDSM4(ah[nxt][3], aBn + kSw[0] + (uint32_t)(3 * 16 * PITCH));
                    if (m == 10)
                        LDSM4(bh[nxt][0], bBn + kSw[0] + (uint32_t)(0 * 16 * PITCH));
                    if (m == 12)
                        LDSM4(bh[nxt][1], bBn + kSw[0] + (uint32_t)(1 * 16 * PITCH));
                }
            }
        }

        // wait for chunk c+2 (issued a full chunk-body ago), then barrier
        // (wait -> barrier -> read = required cp.async visibility order)
        if (c + 1 < KC) {
            CP_WAIT(0);
            __syncthreads();
        }
    }

    // ---- epilogue: compile-time fp32/fp16 output ----
    #pragma unroll
    for (int i = 0; i < 4; i++) {
        const int row = bm + wm * 64 + i * 16 + (lane >> 2);
        #pragma unroll
        for (int j = 0; j < 4; j++) {
            const int col = bn + wn * 32 + j * 8 + (lane & 3) * 2;
            float b0 = 0.f, b1 = 0.f;
            if (bias) { b0 = bias[col]; b1 = bias[col + 1]; }
            const float v00 = acc[i][j][0] + b0, v01 = acc[i][j][1] + b1;
            const float v10 = acc[i][j][2] + b0, v11 = acc[i][j][3] + b1;
            if (OUT_HALF) {
                __half2 h0 = __floats2half2_rn(v00, v01);
                __half2 h1 = __floats2half2_rn(v10, v11);
                *(__half2*)(Ch + (size_t)row * N + col)       = h0;
                *(__half2*)(Ch + (size_t)(row + 8) * N + col) = h1;
            } else {
                *(float2*)(C + (size_t)row * N + col)       = make_float2(v00, v01);
                *(float2*)(C + (size_t)(row + 8) * N + col) = make_float2(v10, v11);
            }
        }
    }
}

// ---------------------------------------------------------------------------
// Merged fp32 -> fp16 conversion: x, Wqkv, Wout in one grid-stride launch.
// ---------------------------------------------------------------------------
#define N4_X  (NTOK * CDIM / 4)
#define N4_W1 (C3 * CDIM / 4)
#define N4_W2 (CDIM * CDIM / 4)

__global__ __launch_bounds__(256) void cvt_all_kernel(
    const float* __restrict__ x,  __half* __restrict__ xh,
    const float* __restrict__ w1, __half* __restrict__ w1h,
    const float* __restrict__ w2, __half* __restrict__ w2h)
{
    const int total = N4_X + N4_W1 + N4_W2;
    for (int i = blockIdx.x * blockDim.x + threadIdx.x; i < total;
         i += gridDim.x * blockDim.x) {
        const float4* s;
        __half* d;
        int k;
        if (i < N4_X)              { s = (const float4*)x;  d = xh;  k = i; }
        else if (i < N4_X + N4_W1) { s = (const float4*)w1; d = w1h; k = i - N4_X; }
        else                       { s = (const float4*)w2; d = w2h; k = i - N4_X - N4_W1; }
        const float4 v = s[k];
        __half2 h0 = __floats2half2_rn(v.x, v.y);
        __half2 h1 = __floats2half2_rn(v.z, v.w);
        uint2 r;
        r.x = *(uint32_t*)&h0;
        r.y = *(uint32_t*)&h1;
        *(uint2*)(d + (size_t)k * 4) = r;
    }
}

// ---------------------------------------------------------------------------
// Attention over heads — register-tiled (R10 layout), fp16 in/out (R13).
// ---------------------------------------------------------------------------
#define TOKPC  8
#define RPITCH 68
#define POFF   3264
#define TPITCH 3544
#define ATTN_SMEM (TOKPC * TPITCH * 4)

__global__ __launch_bounds__(128) void attn_kernel(
    const __half* __restrict__ qkv, __half* __restrict__ y)
{
    extern __shared__ float sh[];
    const int tid = threadIdx.x;
    const int tokBlk = blockIdx.x * TOKPC;

    const uint4* src = (const uint4*)(qkv + (size_t)tokBlk * C3);
    #pragma unroll
    for (int it = 0; it < (TOKPC * 384) / 128; it++) {
        const int i  = it * 128 + tid;
        const int t  = i / 384;
        const int idx = i % 384;
        const int rr = idx >> 3;
        const int c8 = idx & 7;
        const uint4 u = src[i];
        float* dst = sh + t * TPITCH + rr * RPITCH + c8 * 8;
        const __half2* hp = (const __half2*)&u;
        #pragma unroll
        for (int q = 0; q < 4; q++) {
            const float2 f = __half22float2(hp[q]);
            dst[q * 2 + 0] = f.x;
            dst[q * 2 + 1] = f.y;
        }
    }
    __syncthreads();

    const int tok = tid >> 4;
    const int j   = tid & 15;
    const int I   = j >> 2;
    const int J   = j & 3;
    float* tb = sh + tok * TPITCH;

    float s[4][4];
    #pragma unroll
    for (int r = 0; r < 4; r++)
        #pragma unroll
        for (int c = 0; c < 4; c++) s[r][c] = 0.0f;

    #pragma unroll
    for (int dd = 0; dd < 16; dd++) {
        float4 qv[4], kv[4];
        #pragma unroll
        for (int r = 0; r < 4; r++)
            qv[r] = *(const float4*)(tb + (12 * I + 3 * r) * RPITCH + dd * 4);
        #pragma unroll
        for (int c = 0; c < 4; c++)
            kv[c] = *(const float4*)(tb + (12 * J + 3 * c + 1) * RPITCH + dd * 4);
        #pragma unroll
        for (int r = 0; r < 4; r++)
            #pragma unroll
            for (int c = 0; c < 4; c++)
                s[r][c] += qv[r].x * kv[c].x + qv[r].y * kv[c].y
                         + qv[r].z * kv[c].z + qv[r].w * kv[c].w;
    }

    float den[4];
    #pragma unroll
    for (int r = 0; r < 4; r++) {
        float mx = fmaxf(fmaxf(s[r][0], s[r][1]), fmaxf(s[r][2], s[r][3]));
        mx = fmaxf(mx, __shfl_xor_sync(0xFFFFFFFFu, mx, 1));
        mx = fmaxf(mx, __shfl_xor_sync(0xFFFFFFFFu, mx, 2));
        float sum = 0.0f;
        #pragma unroll
        for (int c = 0; c < 4; c++) {
            s[r][c] = __expf((s[r][c] - mx) * 0.125f);
            sum += s[r][c];
        }
        sum += __shfl_xor_sync(0xFFFFFFFFu, sum, 1);
        sum += __shfl_xor_sync(0xFFFFFFFFu, sum, 2);
        den[r] = 1.0f / sum;
    }

    float* P = tb + POFF;
    #pragma unroll
    for (int r = 0; r < 4; r++)
        #pragma unroll
        for (int c = 0; c < 4; c++)
            P[(4 * I + r) * 17 + (4 * J + c)] = s[r][c];
    __syncwarp();

    float o[4][16];
    #pragma unroll
    for (int r = 0; r < 4; r++)
        #pragma unroll
        for (int cc = 0; cc < 16; cc++) o[r][cc] = 0.0f;

    #pragma unroll
    for (int g = 0; g < 16; g++) {
        float a[4];
        #pragma unroll
        for (int r = 0; r < 4; r++) a[r] = P[(4 * I + r) * 17 + g];
        const float* vr = tb + (3 * g + 2) * RPITCH + 16 * J;
        float4 v0 = *(const float4*)(vr);
        float4 v1 = *(const float4*)(vr + 4);
        float4 v2 = *(const float4*)(vr + 8);
        float4 v3 = *(const float4*)(vr + 12);
        #pragma unroll
        for (int r = 0; r < 4; r++) {
            o[r][0]  += a[r] * v0.x;  o[r][1]  += a[r] * v0.y;
            o[r][2]  += a[r] * v0.z;  o[r][3]  += a[r] * v0.w;
            o[r][4]  += a[r] * v1.x;  o[r][5]  += a[r] * v1.y;
            o[r][6]  += a[r] * v1.z;  o[r][7]  += a[r] * v1.w;
            o[r][8]  += a[r] * v2.x;  o[r][9]  += a[r] * v2.y;
            o[r][10] += a[r] * v2.z;  o[r][11] += a[r] * v2.w;
            o[r][12] += a[r] * v3.x;  o[r][13] += a[r] * v3.y;
            o[r][14] += a[r] * v3.z;  o[r][15] += a[r] * v3.w;
        }
    }

    __half* yt = y + (size_t)(tokBlk + tok) * CDIM;
    #pragma unroll
    for (int r = 0; r < 4; r++) {
        const int h = 4 * I + r;
        #pragma unroll
        for (int qq = 0; qq < 2; qq++) {
            __half2 p0 = __floats2half2_rn(o[r][qq*8+0] * den[r], o[r][qq*8+1] * den[r]);
            __half2 p1 = __floats2half2_rn(o[r][qq*8+2] * den[r], o[r][qq*8+3] * den[r]);
            __half2 p2 = __floats2half2_rn(o[r][qq*8+4] * den[r], o[r][qq*8+5] * den[r]);
            __half2 p3 = __floats2half2_rn(o[r][qq*8+6] * den[r], o[r][qq*8+7] * den[r]);
            uint4 w;
            w.x = *(uint32_t*)&p0; w.y = *(uint32_t*)&p1;
            w.z = *(uint32_t*)&p2; w.w = *(uint32_t*)&p3;
            *(uint4*)(yt + h * 64 + 16 * J + qq * 8) = w;
        }
    }
}

// ---------------------------------------------------------------------------
extern "C" void kernel_launch(void* const* d_in, const int* in_sizes, int n_in,
                              void* d_out, int out_size)
{
    const float* x    = (const float*)d_in[0];
    const float* Wqkv = (const float*)d_in[1];
    const float* Wout = (const float*)d_in[2];
    const float* bout = (const float*)d_in[3];
    float* out = (float*)d_out;

    __half *qkvh, *yh, *xh, *w1h, *w2h;
    cudaGetSymbolAddress((void**)&qkvh, g_qkvh);
    cudaGetSymbolAddress((void**)&yh,   g_yh);
    cudaGetSymbolAddress((void**)&xh,   g_xh);
    cudaGetSymbolAddress((void**)&w1h,  g_w1h);
    cudaGetSymbolAddress((void**)&w2h,  g_w2h);

    cudaFuncSetAttribute(f16_gemm<true>,  cudaFuncAttributeMaxDynamicSharedMemorySize, SMEM_B);
    cudaFuncSetAttribute(f16_gemm<false>, cudaFuncAttributeMaxDynamicSharedMemorySize, SMEM_B);
    cudaFuncSetAttribute(attn_kernel,     cudaFuncAttributeMaxDynamicSharedMemorySize, ATTN_SMEM);

    // merged fp16 conversion (x, Wqkv, Wout)
    cvt_all_kernel<<<2960, 256>>>(x, xh, Wqkv, w1h, Wout, w2h);

    // GEMM1: qkvh = xh @ w1h^T   (16384 x 3072, K=1024), fp16 out
    f16_gemm<true><<<dim3(C3 / 128, NTOK / 128), 256, SMEM_B>>>(
        xh, w1h, nullptr, nullptr, qkvh, NTOK, C3);

    // attention over heads (fp16 in/out)
    attn_kernel<<<NTOK / TOKPC, 128, ATTN_SMEM>>>(qkvh, yh);

    // GEMM2: out = yh @ w2h^T + bout   (16384 x 1024, K=1024), fp32 out
    f16_gemm<false><<<dim3(CDIM / 128, NTOK / 128), 256, SMEM_B>>>(
        yh, w2h, bout, out, nullptr, NTOK, CDIM);
}

// round 16
// speedup vs baseline: 1.0240x; 1.0240x over previous
#include <cuda_runtime.h>
#include <cuda_fp16.h>
#include <stdint.h>
#include <math.h>

// ---------------- problem constants ----------------
#define CDIM   1024
#define NTOK   16384             // B*T = 4*4096
#define C3     (3 * CDIM)        // 3072

// ---------------- scratch (allocation-free rule) ----------------
__device__ __half g_qkvh[(size_t)NTOK * C3];    // fp16 qkv
__device__ __half g_yh [(size_t)NTOK * CDIM];   // fp16 y
__device__ __half g_xh [(size_t)NTOK * CDIM];
__device__ __half g_w1h[(size_t)C3 * CDIM];
__device__ __half g_w2h[(size_t)CDIM * CDIM];

// ---------------- PTX helpers (baseline sm_80+ only) ----------------
__device__ __forceinline__ uint32_t smem_u32(const void* p) {
    uint32_t a;
    asm("{ .reg .u64 t; cvta.to.shared.u64 t, %1; cvt.u32.u64 %0, t; }"
        : "=r"(a) : "l"(p));
    return a;
}

#define CP_ASYNC16(dst_u32, src_ptr) \
    asm volatile("cp.async.cg.shared.global [%0], [%1], 16;" \
                 :: "r"(dst_u32), "l"(src_ptr) : "memory")
#define CP_COMMIT() asm volatile("cp.async.commit_group;" ::: "memory")
#define CP_WAIT(n)  asm volatile("cp.async.wait_group %0;" :: "n"(n) : "memory")

#define LDSM4(r, addr) \
    asm volatile("ldmatrix.sync.aligned.m8n8.x4.shared.b16 {%0,%1,%2,%3}, [%4];" \
        : "=r"((r)[0]), "=r"((r)[1]), "=r"((r)[2]), "=r"((r)[3]) : "r"(addr))

// single-pass fp16 m16n8k16, fp32 accumulate
#define MMA_F16(d, a, b0, b1) \
    asm volatile("mma.sync.aligned.m16n8k16.row.col.f32.f16.f16.f32 " \
        "{%0,%1,%2,%3}, {%4,%5,%6,%7}, {%8,%9}, {%0,%1,%2,%3};" \
        : "+f"((d)[0]), "+f"((d)[1]), "+f"((d)[2]), "+f"((d)[3]) \
        : "r"((a)[0]), "r"((a)[1]), "r"((a)[2]), "r"((a)[3]), "r"(b0), "r"(b1))

// ---------------- smem geometry (XOR swizzle, 128 B rows) ----------------
#define PITCH   128
#define TILE_B  (128 * PITCH)      // 16384 B
#define OFF_B   TILE_B
#define STAGE_B (2 * TILE_B)       // 32768 B
#define NSTG    3
#define SMEM_B  (NSTG * STAGE_B)   // 98304 B -> 2 CTAs/SM
#define BKC     64                 // K halves per chunk (4 k16 steps)
#define KFIX    1024               // compile-time K (both GEMMs)
#define KC      (KFIX / BKC)       // 16 chunks, fully unrolled

// wide (128x256) variant geometry
#define BW_B    (256 * PITCH)          // 32768
#define STW_B   (TILE_B + BW_B)        // 49152
#define SMEM_W  (NSTG * STW_B)         // 147456 -> 1 CTA/SM (512 thr)

// ---------------------------------------------------------------------------
// GEMM 128x128 (R14-exact): C = A @ B^T (+bias); fp16 in, fp32 accum.
// 256 thr, 8 warps (64x32), 3-stage cp.async, 2 CTAs/SM, full KC unroll.
// ---------------------------------------------------------------------------
template <bool OUT_HALF>
__global__ __launch_bounds__(256, 2) void f16_gemm(
    const __half* __restrict__ A, const __half* __restrict__ B,
    const float* __restrict__ bias, float* __restrict__ C,
    __half* __restrict__ Ch, int M, int N)
{
    extern __shared__ char sm[];
    const uint32_t sbase = smem_u32(sm);

    const int tid  = threadIdx.x;
    const int lane = tid & 31;
    const int wid  = tid >> 5;
    const int wm   = wid & 1;
    const int wn   = wid >> 1;
    const int bm   = blockIdx.y * 128;
    const int bn   = blockIdx.x * 128;

    const int lr = tid >> 1;
    const int lh = tid & 1;
    const __half* gA = A + (size_t)(bm + lr) * KFIX + lh * 32;
    const __half* gB = B + (size_t)(bn + lr) * KFIX + lh * 32;
    uint32_t sw[4];
    #pragma unroll
    for (int j = 0; j < 4; j++) sw[j] = (uint32_t)(((lh * 4 + j) ^ (lr & 7)) << 4);
    const uint32_t sRowBase = (uint32_t)(lr * PITCH);

    const int l8 = lane & 7;
    const int cg = lane >> 4;
    const uint32_t aRow = (uint32_t)((wm * 64 + (lane & 15)) * PITCH);
    const uint32_t bRow = (uint32_t)((wn * 32 + (lane & 15)) * PITCH);
    uint32_t kSw[4];
    #pragma unroll
    for (int s = 0; s < 4; s++)
        kSw[s] = (uint32_t)(((s * 2 + cg) ^ l8) << 4);

    float acc[4][4][4];
    #pragma unroll
    for (int i = 0; i < 4; i++)
        #pragma unroll
        for (int j = 0; j < 4; j++)
            #pragma unroll
            for (int q = 0; q < 4; q++) acc[i][j][q] = 0.0f;

    auto issue = [&](int stg, int ko) {
        const uint32_t dA = sbase + (uint32_t)stg * STAGE_B + sRowBase;
        const uint32_t dB = dA + OFF_B;
        const __half* sa = gA + ko;
        const __half* sb = gB + ko;
        #pragma unroll
        for (int j = 0; j < 4; j++) {
            CP_ASYNC16(dA + sw[j], sa + j * 8);
            CP_ASYNC16(dB + sw[j], sb + j * 8);
        }
    };

    issue(0, 0);   CP_COMMIT();
    issue(1, BKC); CP_COMMIT();

    uint32_t ah[2][4][4], bh[2][2][4];

    #pragma unroll
    for (int c = 0; c < KC; c++) {
        if (c == KC - 1) { CP_WAIT(0); } else { CP_WAIT(1); }
        __syncthreads();
        if (c + 2 < KC) { issue((c + 2) % NSTG, (c + 2) * BKC); CP_COMMIT(); }

        const uint32_t stg = sbase + (uint32_t)((c % NSTG) * STAGE_B);
        const uint32_t aB  = stg + aRow;
        const uint32_t bB  = stg + OFF_B + bRow;

        #pragma unroll
        for (int i = 0; i < 4; i++) LDSM4(ah[0][i], aB + kSw[0] + (uint32_t)(i * 16 * PITCH));
        #pragma unroll
        for (int p = 0; p < 2; p++) LDSM4(bh[0][p], bB + kSw[0] + (uint32_t)(p * 16 * PITCH));

        #pragma unroll
        for (int s = 0; s < 4; s++) {
            const int cur = s & 1;
            const int nxt = cur ^ 1;
            #pragma unroll
            for (int m = 0; m < 16; m++) {
                const int i = m >> 2, j = m & 3;
                const int nb = j >> 1, jj = j & 1;
                const uint32_t b0 = jj ? bh[cur][nb][1] : bh[cur][nb][0];
                const uint32_t b1 = jj ? bh[cur][nb][3] : bh[cur][nb][2];
                MMA_F16(acc[i][j], ah[cur][i], b0, b1);
                if (s < 3) {
                    if (m == 2)
                        LDSM4(ah[nxt][0], aB + kSw[s + 1] + (uint32_t)(0 * 16 * PITCH));
                    if (m == 4)
                        LDSM4(ah[nxt][1], aB + kSw[s + 1] + (uint32_t)(1 * 16 * PITCH));
                    if (m == 6)
                        LDSM4(ah[nxt][2], aB + kSw[s + 1] + (uint32_t)(2 * 16 * PITCH));
                    if (m == 8)
                        LDSM4(ah[nxt][3], aB + kSw[s + 1] + (uint32_t)(3 * 16 * PITCH));
                    if (m == 10)
                        LDSM4(bh[nxt][0], bB + kSw[s + 1] + (uint32_t)(0 * 16 * PITCH));
                    if (m == 12)
                        LDSM4(bh[nxt][1], bB + kSw[s + 1] + (uint32_t)(1 * 16 * PITCH));
                }
            }
        }
    }

    #pragma unroll
    for (int i = 0; i < 4; i++) {
        const int row = bm + wm * 64 + i * 16 + (lane >> 2);
        #pragma unroll
        for (int j = 0; j < 4; j++) {
            const int col = bn + wn * 32 + j * 8 + (lane & 3) * 2;
            float b0 = 0.f, b1 = 0.f;
            if (bias) { b0 = bias[col]; b1 = bias[col + 1]; }
            const float v00 = acc[i][j][0] + b0, v01 = acc[i][j][1] + b1;
            const float v10 = acc[i][j][2] + b0, v11 = acc[i][j][3] + b1;
            if (OUT_HALF) {
                __half2 h0 = __floats2half2_rn(v00, v01);
                __half2 h1 = __floats2half2_rn(v10, v11);
                *(__half2*)(Ch + (size_t)row * N + col)       = h0;
                *(__half2*)(Ch + (size_t)(row + 8) * N + col) = h1;
            } else {
                *(float2*)(C + (size_t)row * N + col)       = make_float2(v00, v01);
                *(float2*)(C + (size_t)(row + 8) * N + col) = make_float2(v10, v11);
            }
        }
    }
}

// ---------------------------------------------------------------------------
// GEMM 128x256 "wide": 512 threads, 16 warps of the SAME 64x32 warp tile.
// 1 CTA/SM (16 warps = 4/SMSP, same SMSP occupancy), grid 12x128 = 1536 CTAs
// over 148 slots -> 10.38 waves (94.4% util vs 86.5% at 128x128).
// fp16 output (GEMM1 -> qkvh).
// ---------------------------------------------------------------------------
__global__ __launch_bounds__(512, 1) void f16_gemm_wide(
    const __half* __restrict__ A, const __half* __restrict__ B,
    __half* __restrict__ Ch, int M, int N)
{
    extern __shared__ char sm[];
    const uint32_t sbase = smem_u32(sm);

    const int tid  = threadIdx.x;
    const int lane = tid & 31;
    const int wid  = tid >> 5;          // 0..15
    const int wm   = wid & 1;           // M half
    const int wn   = wid >> 1;          // N slice 0..7
    const int bm   = blockIdx.y * 128;
    const int bn   = blockIdx.x * 256;

    // ---- A loader: 128 rows x 8 chunks; thread -> (row tid>>2, 2 chunks) ----
    const int lrA = tid >> 2;           // 0..127
    const int lcA = (tid & 3) * 2;      // chunk 0,2,4,6
    const __half* gA = A + (size_t)(bm + lrA) * KFIX + lcA * 8;
    uint32_t swA[2];
    #pragma unroll
    for (int j = 0; j < 2; j++) swA[j] = (uint32_t)(((lcA + j) ^ (lrA & 7)) << 4);
    const uint32_t sRowA = (uint32_t)(lrA * PITCH);

    // ---- B loader: 256 rows x 8 chunks; thread -> (row tid>>1, 4 chunks) ----
    const int lrB = tid >> 1;           // 0..255
    const int lhB = tid & 1;
    const __half* gB = B + (size_t)(bn + lrB) * KFIX + lhB * 32;
    uint32_t swB[4];
    #pragma unroll
    for (int j = 0; j < 4; j++) swB[j] = (uint32_t)(((lhB * 4 + j) ^ (lrB & 7)) << 4);
    const uint32_t sRowB = (uint32_t)(OFF_B + lrB * PITCH);

    // ---- ldmatrix lane addressing ----
    const int l8 = lane & 7;
    const int cg = lane >> 4;
    const uint32_t aRow = (uint32_t)((wm * 64 + (lane & 15)) * PITCH);
    const uint32_t bRow = (uint32_t)((wn * 32 + (lane & 15)) * PITCH);
    uint32_t kSw[4];
    #pragma unroll
    for (int s = 0; s < 4; s++)
        kSw[s] = (uint32_t)(((s * 2 + cg) ^ l8) << 4);

    float acc[4][4][4];
    #pragma unroll
    for (int i = 0; i < 4; i++)
        #pragma unroll
        for (int j = 0; j < 4; j++)
            #pragma unroll
            for (int q = 0; q < 4; q++) acc[i][j][q] = 0.0f;

    auto issue = [&](int stg, int ko) {
        const uint32_t dA = sbase + (uint32_t)stg * STW_B + sRowA;
        const uint32_t dB = sbase + (uint32_t)stg * STW_B + sRowB;
        const __half* sa = gA + ko;
        const __half* sb = gB + ko;
        #pragma unroll
        for (int j = 0; j < 2; j++) CP_ASYNC16(dA + swA[j], sa + j * 8);
        #pragma unroll
        for (int j = 0; j < 4; j++) CP_ASYNC16(dB + swB[j], sb + j * 8);
    };

    issue(0, 0);   CP_COMMIT();
    issue(1, BKC); CP_COMMIT();

    uint32_t ah[2][4][4], bh[2][2][4];

    #pragma unroll
    for (int c = 0; c < KC; c++) {
        if (c == KC - 1) { CP_WAIT(0); } else { CP_WAIT(1); }
        __syncthreads();
        if (c + 2 < KC) { issue((c + 2) % NSTG, (c + 2) * BKC); CP_COMMIT(); }

        const uint32_t stg = sbase + (uint32_t)((c % NSTG) * STW_B);
        const uint32_t aB  = stg + aRow;
        const uint32_t bB  = stg + OFF_B + bRow;

        #pragma unroll
        for (int i = 0; i < 4; i++) LDSM4(ah[0][i], aB + kSw[0] + (uint32_t)(i * 16 * PITCH));
        #pragma unroll
        for (int p = 0; p < 2; p++) LDSM4(bh[0][p], bB + kSw[0] + (uint32_t)(p * 16 * PITCH));

        #pragma unroll
        for (int s = 0; s < 4; s++) {
            const int cur = s & 1;
            const int nxt = cur ^ 1;
            #pragma unroll
            for (int m = 0; m < 16; m++) {
                const int i = m >> 2, j = m & 3;
                const int nb = j >> 1, jj = j & 1;
                const uint32_t b0 = jj ? bh[cur][nb][1] : bh[cur][nb][0];
                const uint32_t b1 = jj ? bh[cur][nb][3] : bh[cur][nb][2];
                MMA_F16(acc[i][j], ah[cur][i], b0, b1);
                if (s < 3) {
                    if (m == 2)
                        LDSM4(ah[nxt][0], aB + kSw[s + 1] + (uint32_t)(0 * 16 * PITCH));
                    if (m == 4)
                        LDSM4(ah[nxt][1], aB + kSw[s + 1] + (uint32_t)(1 * 16 * PITCH));
                    if (m == 6)
                        LDSM4(ah[nxt][2], aB + kSw[s + 1] + (uint32_t)(2 * 16 * PITCH));
                    if (m == 8)
                        LDSM4(ah[nxt][3], aB + kSw[s + 1] + (uint32_t)(3 * 16 * PITCH));
                    if (m == 10)
                        LDSM4(bh[nxt][0], bB + kSw[s + 1] + (uint32_t)(0 * 16 * PITCH));
                    if (m == 12)
                        LDSM4(bh[nxt][1], bB + kSw[s + 1] + (uint32_t)(1 * 16 * PITCH));
                }
            }
        }
    }

    // ---- epilogue: fp16 output ----
    #pragma unroll
    for (int i = 0; i < 4; i++) {
        const int row = bm + wm * 64 + i * 16 + (lane >> 2);
        #pragma unroll
        for (int j = 0; j < 4; j++) {
            const int col = bn + wn * 32 + j * 8 + (lane & 3) * 2;
            __half2 h0 = __floats2half2_rn(acc[i][j][0], acc[i][j][1]);
            __half2 h1 = __floats2half2_rn(acc[i][j][2], acc[i][j][3]);
            *(__half2*)(Ch + (size_t)row * N + col)       = h0;
            *(__half2*)(Ch + (size_t)(row + 8) * N + col) = h1;
        }
    }
}

// ---------------------------------------------------------------------------
// Merged fp32 -> fp16 conversion: x, Wqkv, Wout in one grid-stride launch.
// ---------------------------------------------------------------------------
#define N4_X  (NTOK * CDIM / 4)
#define N4_W1 (C3 * CDIM / 4)
#define N4_W2 (CDIM * CDIM / 4)

__global__ __launch_bounds__(256) void cvt_all_kernel(
    const float* __restrict__ x,  __half* __restrict__ xh,
    const float* __restrict__ w1, __half* __restrict__ w1h,
    const float* __restrict__ w2, __half* __restrict__ w2h)
{
    const int total = N4_X + N4_W1 + N4_W2;
    for (int i = blockIdx.x * blockDim.x + threadIdx.x; i < total;
         i += gridDim.x * blockDim.x) {
        const float4* s;
        __half* d;
        int k;
        if (i < N4_X)              { s = (const float4*)x;  d = xh;  k = i; }
        else if (i < N4_X + N4_W1) { s = (const float4*)w1; d = w1h; k = i - N4_X; }
        else                       { s = (const float4*)w2; d = w2h; k = i - N4_X - N4_W1; }
        const float4 v = s[k];
        __half2 h0 = __floats2half2_rn(v.x, v.y);
        __half2 h1 = __floats2half2_rn(v.z, v.w);
        uint2 r;
        r.x = *(uint32_t*)&h0;
        r.y = *(uint32_t*)&h1;
        *(uint2*)(d + (size_t)k * 4) = r;
    }
}

// ---------------------------------------------------------------------------
// Attention over heads — register-tiled (R10 layout), fp16 in/out (R13).
// ---------------------------------------------------------------------------
#define TOKPC  8
#define RPITCH 68
#define POFF   3264
#define TPITCH 3544
#define ATTN_SMEM (TOKPC * TPITCH * 4)

__global__ __launch_bounds__(128) void attn_kernel(
    const __half* __restrict__ qkv, __half* __restrict__ y)
{
    extern __shared__ float sh[];
    const int tid = threadIdx.x;
    const int tokBlk = blockIdx.x * TOKPC;

    const uint4* src = (const uint4*)(qkv + (size_t)tokBlk * C3);
    #pragma unroll
    for (int it = 0; it < (TOKPC * 384) / 128; it++) {
        const int i  = it * 128 + tid;
        const int t  = i / 384;
        const int idx = i % 384;
        const int rr = idx >> 3;
        const int c8 = idx & 7;
        const uint4 u = src[i];
        float* dst = sh + t * TPITCH + rr * RPITCH + c8 * 8;
        const __half2* hp = (const __half2*)&u;
        #pragma unroll
        for (int q = 0; q < 4; q++) {
            const float2 f = __half22float2(hp[q]);
            dst[q * 2 + 0] = f.x;
            dst[q * 2 + 1] = f.y;
        }
    }
    __syncthreads();

    const int tok = tid >> 4;
    const int j   = tid & 15;
    const int I   = j >> 2;
    const int J   = j & 3;
    float* tb = sh + tok * TPITCH;

    float s[4][4];
    #pragma unroll
    for (int r = 0; r < 4; r++)
        #pragma unroll
        for (int c = 0; c < 4; c++) s[r][c] = 0.0f;

    #pragma unroll
    for (int dd = 0; dd < 16; dd++) {
        float4 qv[4], kv[4];
        #pragma unroll
        for (int r = 0; r < 4; r++)
            qv[r] = *(const float4*)(tb + (12 * I + 3 * r) * RPITCH + dd * 4);
        #pragma unroll
        for (int c = 0; c < 4; c++)
            kv[c] = *(const float4*)(tb + (12 * J + 3 * c + 1) * RPITCH + dd * 4);
        #pragma unroll
        for (int r = 0; r < 4; r++)
            #pragma unroll
            for (int c = 0; c < 4; c++)
                s[r][c] += qv[r].x * kv[c].x + qv[r].y * kv[c].y
                         + qv[r].z * kv[c].z + qv[r].w * kv[c].w;
    }

    float den[4];
    #pragma unroll
    for (int r = 0; r < 4; r++) {
        float mx = fmaxf(fmaxf(s[r][0], s[r][1]), fmaxf(s[r][2], s[r][3]));
        mx = fmaxf(mx, __shfl_xor_sync(0xFFFFFFFFu, mx, 1));
        mx = fmaxf(mx, __shfl_xor_sync(0xFFFFFFFFu, mx, 2));
        float sum = 0.0f;
        #pragma unroll
        for (int c = 0; c < 4; c++) {
            s[r][c] = __expf((s[r][c] - mx) * 0.125f);
            sum += s[r][c];
        }
        sum += __shfl_xor_sync(0xFFFFFFFFu, sum, 1);
        sum += __shfl_xor_sync(0xFFFFFFFFu, sum, 2);
        den[r] = 1.0f / sum;
    }

    float* P = tb + POFF;
    #pragma unroll
    for (int r = 0; r < 4; r++)
        #pragma unroll
        for (int c = 0; c < 4; c++)
            P[(4 * I + r) * 17 + (4 * J + c)] = s[r][c];
    __syncwarp();

    float o[4][16];
    #pragma unroll
    for (int r = 0; r < 4; r++)
        #pragma unroll
        for (int cc = 0; cc < 16; cc++) o[r][cc] = 0.0f;

    #pragma unroll
    for (int g = 0; g < 16; g++) {
        float a[4];
        #pragma unroll
        for (int r = 0; r < 4; r++) a[r] = P[(4 * I + r) * 17 + g];
        const float* vr = tb + (3 * g + 2) * RPITCH + 16 * J;
        float4 v0 = *(const float4*)(vr);
        float4 v1 = *(const float4*)(vr + 4);
        float4 v2 = *(const float4*)(vr + 8);
        float4 v3 = *(const float4*)(vr + 12);
        #pragma unroll
        for (int r = 0; r < 4; r++) {
            o[r][0]  += a[r] * v0.x;  o[r][1]  += a[r] * v0.y;
            o[r][2]  += a[r] * v0.z;  o[r][3]  += a[r] * v0.w;
            o[r][4]  += a[r] * v1.x;  o[r][5]  += a[r] * v1.y;
            o[r][6]  += a[r] * v1.z;  o[r][7]  += a[r] * v1.w;
            o[r][8]  += a[r] * v2.x;  o[r][9]  += a[r] * v2.y;
            o[r][10] += a[r] * v2.z;  o[r][11] += a[r] * v2.w;
            o[r][12] += a[r] * v3.x;  o[r][13] += a[r] * v3.y;
            o[r][14] += a[r] * v3.z;  o[r][15] += a[r] * v3.w;
        }
    }

    __half* yt = y + (size_t)(tokBlk + tok) * CDIM;
    #pragma unroll
    for (int r = 0; r < 4; r++) {
        const int h = 4 * I + r;
        #pragma unroll
        for (int qq = 0; qq < 2; qq++) {
            __half2 p0 = __floats2half2_rn(o[r][qq*8+0] * den[r], o[r][qq*8+1] * den[r]);
            __half2 p1 = __floats2half2_rn(o[r][qq*8+2] * den[r], o[r][qq*8+3] * den[r]);
            __half2 p2 = __floats2half2_rn(o[r][qq*8+4] * den[r], o[r][qq*8+5] * den[r]);
            __half2 p3 = __floats2half2_rn(o[r][qq*8+6] * den[r], o[r][qq*8+7] * den[r]);
            uint4 w;
            w.x = *(uint32_t*)&p0; w.y = *(uint32_t*)&p1;
            w.z = *(uint32_t*)&p2; w.w = *(uint32_t*)&p3;
            *(uint4*)(yt + h * 64 + 16 * J + qq * 8) = w;
        }
    }
}

// ---------------------------------------------------------------------------
extern "C" void kernel_launch(void* const* d_in, const int* in_sizes, int n_in,
                              void* d_out, int out_size)
{
    const float* x    = (const float*)d_in[0];
    const float* Wqkv = (const float*)d_in[1];
    const float* Wout = (const float*)d_in[2];
    const float* bout = (const float*)d_in[3];
    float* out = (float*)d_out;

    __half *qkvh, *yh, *xh, *w1h, *w2h;
    cudaGetSymbolAddress((void**)&qkvh, g_qkvh);
    cudaGetSymbolAddress((void**)&yh,   g_yh);
    cudaGetSymbolAddress((void**)&xh,   g_xh);
    cudaGetSymbolAddress((void**)&w1h,  g_w1h);
    cudaGetSymbolAddress((void**)&w2h,  g_w2h);

    cudaFuncSetAttribute(f16_gemm<false>, cudaFuncAttributeMaxDynamicSharedMemorySize, SMEM_B);
    cudaFuncSetAttribute(f16_gemm_wide,   cudaFuncAttributeMaxDynamicSharedMemorySize, SMEM_W);
    cudaFuncSetAttribute(attn_kernel,     cudaFuncAttributeMaxDynamicSharedMemorySize, ATTN_SMEM);

    // merged fp16 conversion (x, Wqkv, Wout)
    cvt_all_kernel<<<2960, 256>>>(x, xh, Wqkv, w1h, Wout, w2h);

    // GEMM1: qkvh = xh @ w1h^T   (16384 x 3072, K=1024), 128x256 tiles, fp16 out
    f16_gemm_wide<<<dim3(C3 / 256, NTOK / 128), 512, SMEM_W>>>(
        xh, w1h, qkvh, NTOK, C3);

    // attention over heads (fp16 in/out)
    attn_kernel<<<NTOK / TOKPC, 128, ATTN_SMEM>>>(qkvh, yh);

    // GEMM2: out = yh @ w2h^T + bout   (16384 x 1024, K=1024), 128x128 tiles
    f16_gemm<false><<<dim3(CDIM / 128, NTOK / 128), 256, SMEM_B>>>(
        yh, w2h, bout, out, nullptr, NTOK, CDIM);
}

// round 17
// speedup vs baseline: 1.0718x; 1.0466x over previous
#include <cuda_runtime.h>
#include <cuda_fp16.h>
#include <stdint.h>
#include <math.h>

// ---------------- problem constants ----------------
#define CDIM   1024
#define NTOK   16384             // B*T = 4*4096
#define C3     (3 * CDIM)        // 3072

// ---------------- scratch (allocation-free rule) ----------------
__device__ __half g_qkvh[(size_t)NTOK * C3];    // fp16 qkv
__device__ __half g_yh [(size_t)NTOK * CDIM];   // fp16 y
__device__ __half g_xh [(size_t)NTOK * CDIM];
__device__ __half g_w1h[(size_t)C3 * CDIM];
__device__ __half g_w2h[(size_t)CDIM * CDIM];

// ---------------- PTX helpers (baseline sm_80+ only) ----------------
__device__ __forceinline__ uint32_t smem_u32(const void* p) {
    uint32_t a;
    asm("{ .reg .u64 t; cvta.to.shared.u64 t, %1; cvt.u32.u64 %0, t; }"
        : "=r"(a) : "l"(p));
    return a;
}

#define CP_ASYNC16(dst_u32, src_ptr) \
    asm volatile("cp.async.cg.shared.global [%0], [%1], 16;" \
                 :: "r"(dst_u32), "l"(src_ptr) : "memory")
#define CP_COMMIT() asm volatile("cp.async.commit_group;" ::: "memory")
#define CP_WAIT(n)  asm volatile("cp.async.wait_group %0;" :: "n"(n) : "memory")

#define LDSM4(r, addr) \
    asm volatile("ldmatrix.sync.aligned.m8n8.x4.shared.b16 {%0,%1,%2,%3}, [%4];" \
        : "=r"((r)[0]), "=r"((r)[1]), "=r"((r)[2]), "=r"((r)[3]) : "r"(addr))

// single-pass fp16 m16n8k16, fp32 accumulate
#define MMA_F16(d, a, b0, b1) \
    asm volatile("mma.sync.aligned.m16n8k16.row.col.f32.f16.f16.f32 " \
        "{%0,%1,%2,%3}, {%4,%5,%6,%7}, {%8,%9}, {%0,%1,%2,%3};" \
        : "+f"((d)[0]), "+f"((d)[1]), "+f"((d)[2]), "+f"((d)[3]) \
        : "r"((a)[0]), "r"((a)[1]), "r"((a)[2]), "r"((a)[3]), "r"(b0), "r"(b1))

// ---------------- smem geometry (XOR swizzle, 128 B rows) ----------------
#define PITCH   128
#define TILE_B  (128 * PITCH)      // 16384 B
#define OFF_B   TILE_B
#define STAGE_B (2 * TILE_B)       // 32768 B
#define NSTG    3
#define SMEM_B  (NSTG * STAGE_B)   // 98304 B -> 2 CTAs/SM
#define BKC     64                 // K halves per chunk (4 k16 steps)
#define KFIX    1024               // compile-time K (both GEMMs)
#define KC      (KFIX / BKC)       // 16 chunks, fully unrolled

// wide (128x256) variant geometry
#define BW_B    (256 * PITCH)          // 32768
#define STW_B   (TILE_B + BW_B)        // 49152
#define SMEM_W  (NSTG * STW_B)         // 147456 -> 1 CTA/SM (512 thr)

// ---------------------------------------------------------------------------
// GEMM 128x128 (R14-exact): C = A @ B^T (+bias); fp16 in, fp32 accum.
// ---------------------------------------------------------------------------
template <bool OUT_HALF>
__global__ __launch_bounds__(256, 2) void f16_gemm(
    const __half* __restrict__ A, const __half* __restrict__ B,
    const float* __restrict__ bias, float* __restrict__ C,
    __half* __restrict__ Ch, int M, int N)
{
    extern __shared__ char sm[];
    const uint32_t sbase = smem_u32(sm);

    const int tid  = threadIdx.x;
    const int lane = tid & 31;
    const int wid  = tid >> 5;
    const int wm   = wid & 1;
    const int wn   = wid >> 1;
    const int bm   = blockIdx.y * 128;
    const int bn   = blockIdx.x * 128;

    const int lr = tid >> 1;
    const int lh = tid & 1;
    const __half* gA = A + (size_t)(bm + lr) * KFIX + lh * 32;
    const __half* gB = B + (size_t)(bn + lr) * KFIX + lh * 32;
    uint32_t sw[4];
    #pragma unroll
    for (int j = 0; j < 4; j++) sw[j] = (uint32_t)(((lh * 4 + j) ^ (lr & 7)) << 4);
    const uint32_t sRowBase = (uint32_t)(lr * PITCH);

    const int l8 = lane & 7;
    const int cg = lane >> 4;
    const uint32_t aRow = (uint32_t)((wm * 64 + (lane & 15)) * PITCH);
    const uint32_t bRow = (uint32_t)((wn * 32 + (lane & 15)) * PITCH);
    uint32_t kSw[4];
    #pragma unroll
    for (int s = 0; s < 4; s++)
        kSw[s] = (uint32_t)(((s * 2 + cg) ^ l8) << 4);

    float acc[4][4][4];
    #pragma unroll
    for (int i = 0; i < 4; i++)
        #pragma unroll
        for (int j = 0; j < 4; j++)
            #pragma unroll
            for (int q = 0; q < 4; q++) acc[i][j][q] = 0.0f;

    auto issue = [&](int stg, int ko) {
        const uint32_t dA = sbase + (uint32_t)stg * STAGE_B + sRowBase;
        const uint32_t dB = dA + OFF_B;
        const __half* sa = gA + ko;
        const __half* sb = gB + ko;
        #pragma unroll
        for (int j = 0; j < 4; j++) {
            CP_ASYNC16(dA + sw[j], sa + j * 8);
            CP_ASYNC16(dB + sw[j], sb + j * 8);
        }
    };

    issue(0, 0);   CP_COMMIT();
    issue(1, BKC); CP_COMMIT();

    uint32_t ah[2][4][4], bh[2][2][4];

    #pragma unroll
    for (int c = 0; c < KC; c++) {
        if (c == KC - 1) { CP_WAIT(0); } else { CP_WAIT(1); }
        __syncthreads();
        if (c + 2 < KC) { issue((c + 2) % NSTG, (c + 2) * BKC); CP_COMMIT(); }

        const uint32_t stg = sbase + (uint32_t)((c % NSTG) * STAGE_B);
        const uint32_t aB  = stg + aRow;
        const uint32_t bB  = stg + OFF_B + bRow;

        #pragma unroll
        for (int i = 0; i < 4; i++) LDSM4(ah[0][i], aB + kSw[0] + (uint32_t)(i * 16 * PITCH));
        #pragma unroll
        for (int p = 0; p < 2; p++) LDSM4(bh[0][p], bB + kSw[0] + (uint32_t)(p * 16 * PITCH));

        #pragma unroll
        for (int s = 0; s < 4; s++) {
            const int cur = s & 1;
            const int nxt = cur ^ 1;
            #pragma unroll
            for (int m = 0; m < 16; m++) {
                const int i = m >> 2, j = m & 3;
                const int nb = j >> 1, jj = j & 1;
                const uint32_t b0 = jj ? bh[cur][nb][1] : bh[cur][nb][0];
                const uint32_t b1 = jj ? bh[cur][nb][3] : bh[cur][nb][2];
                MMA_F16(acc[i][j], ah[cur][i], b0, b1);
                if (s < 3) {
                    if (m == 2)
                        LDSM4(ah[nxt][0], aB + kSw[s + 1] + (uint32_t)(0 * 16 * PITCH));
                    if (m == 4)
                        LDSM4(ah[nxt][1], aB + kSw[s + 1] + (uint32_t)(1 * 16 * PITCH));
                    if (m == 6)
                        LDSM4(ah[nxt][2], aB + kSw[s + 1] + (uint32_t)(2 * 16 * PITCH));
                    if (m == 8)
                        LDSM4(ah[nxt][3], aB + kSw[s + 1] + (uint32_t)(3 * 16 * PITCH));
                    if (m == 10)
                        LDSM4(bh[nxt][0], bB + kSw[s + 1] + (uint32_t)(0 * 16 * PITCH));
                    if (m == 12)
                        LDSM4(bh[nxt][1], bB + kSw[s + 1] + (uint32_t)(1 * 16 * PITCH));
                }
            }
        }
    }

    #pragma unroll
    for (int i = 0; i < 4; i++) {
        const int row = bm + wm * 64 + i * 16 + (lane >> 2);
        #pragma unroll
        for (int j = 0; j < 4; j++) {
            const int col = bn + wn * 32 + j * 8 + (lane & 3) * 2;
            float b0 = 0.f, b1 = 0.f;
            if (bias) { b0 = bias[col]; b1 = bias[col + 1]; }
            const float v00 = acc[i][j][0] + b0, v01 = acc[i][j][1] + b1;
            const float v10 = acc[i][j][2] + b0, v11 = acc[i][j][3] + b1;
            if (OUT_HALF) {
                __half2 h0 = __floats2half2_rn(v00, v01);
                __half2 h1 = __floats2half2_rn(v10, v11);
                *(__half2*)(Ch + (size_t)row * N + col)       = h0;
                *(__half2*)(Ch + (size_t)(row + 8) * N + col) = h1;
            } else {
                *(float2*)(C + (size_t)row * N + col)       = make_float2(v00, v01);
                *(float2*)(C + (size_t)(row + 8) * N + col) = make_float2(v10, v11);
            }
        }
    }
}

// ---------------------------------------------------------------------------
// GEMM 128x256 "wide" (R16-exact): 512 threads, 16 warps of 64x32.
// ---------------------------------------------------------------------------
__global__ __launch_bounds__(512, 1) void f16_gemm_wide(
    const __half* __restrict__ A, const __half* __restrict__ B,
    __half* __restrict__ Ch, int M, int N)
{
    extern __shared__ char sm[];
    const uint32_t sbase = smem_u32(sm);

    const int tid  = threadIdx.x;
    const int lane = tid & 31;
    const int wid  = tid >> 5;
    const int wm   = wid & 1;
    const int wn   = wid >> 1;
    const int bm   = blockIdx.y * 128;
    const int bn   = blockIdx.x * 256;

    const int lrA = tid >> 2;
    const int lcA = (tid & 3) * 2;
    const __half* gA = A + (size_t)(bm + lrA) * KFIX + lcA * 8;
    uint32_t swA[2];
    #pragma unroll
    for (int j = 0; j < 2; j++) swA[j] = (uint32_t)(((lcA + j) ^ (lrA & 7)) << 4);
    const uint32_t sRowA = (uint32_t)(lrA * PITCH);

    const int lrB = tid >> 1;
    const int lhB = tid & 1;
    const __half* gB = B + (size_t)(bn + lrB) * KFIX + lhB * 32;
    uint32_t swB[4];
    #pragma unroll
    for (int j = 0; j < 4; j++) swB[j] = (uint32_t)(((lhB * 4 + j) ^ (lrB & 7)) << 4);
    const uint32_t sRowB = (uint32_t)(OFF_B + lrB * PITCH);

    const int l8 = lane & 7;
    const int cg = lane >> 4;
    const uint32_t aRow = (uint32_t)((wm * 64 + (lane & 15)) * PITCH);
    const uint32_t bRow = (uint32_t)((wn * 32 + (lane & 15)) * PITCH);
    uint32_t kSw[4];
    #pragma unroll
    for (int s = 0; s < 4; s++)
        kSw[s] = (uint32_t)(((s * 2 + cg) ^ l8) << 4);

    float acc[4][4][4];
    #pragma unroll
    for (int i = 0; i < 4; i++)
        #pragma unroll
        for (int j = 0; j < 4; j++)
            #pragma unroll
            for (int q = 0; q < 4; q++) acc[i][j][q] = 0.0f;

    auto issue = [&](int stg, int ko) {
        const uint32_t dA = sbase + (uint32_t)stg * STW_B + sRowA;
        const uint32_t dB = sbase + (uint32_t)stg * STW_B + sRowB;
        const __half* sa = gA + ko;
        const __half* sb = gB + ko;
        #pragma unroll
        for (int j = 0; j < 2; j++) CP_ASYNC16(dA + swA[j], sa + j * 8);
        #pragma unroll
        for (int j = 0; j < 4; j++) CP_ASYNC16(dB + swB[j], sb + j * 8);
    };

    issue(0, 0);   CP_COMMIT();
    issue(1, BKC); CP_COMMIT();

    uint32_t ah[2][4][4], bh[2][2][4];

    #pragma unroll
    for (int c = 0; c < KC; c++) {
        if (c == KC - 1) { CP_WAIT(0); } else { CP_WAIT(1); }
        __syncthreads();
        if (c + 2 < KC) { issue((c + 2) % NSTG, (c + 2) * BKC); CP_COMMIT(); }

        const uint32_t stg = sbase + (uint32_t)((c % NSTG) * STW_B);
        const uint32_t aB  = stg + aRow;
        const uint32_t bB  = stg + OFF_B + bRow;

        #pragma unroll
        for (int i = 0; i < 4; i++) LDSM4(ah[0][i], aB + kSw[0] + (uint32_t)(i * 16 * PITCH));
        #pragma unroll
        for (int p = 0; p < 2; p++) LDSM4(bh[0][p], bB + kSw[0] + (uint32_t)(p * 16 * PITCH));

        #pragma unroll
        for (int s = 0; s < 4; s++) {
            const int cur = s & 1;
            const int nxt = cur ^ 1;
            #pragma unroll
            for (int m = 0; m < 16; m++) {
                const int i = m >> 2, j = m & 3;
                const int nb = j >> 1, jj = j & 1;
                const uint32_t b0 = jj ? bh[cur][nb][1] : bh[cur][nb][0];
                const uint32_t b1 = jj ? bh[cur][nb][3] : bh[cur][nb][2];
                MMA_F16(acc[i][j], ah[cur][i], b0, b1);
                if (s < 3) {
                    if (m == 2)
                        LDSM4(ah[nxt][0], aB + kSw[s + 1] + (uint32_t)(0 * 16 * PITCH));
                    if (m == 4)
                        LDSM4(ah[nxt][1], aB + kSw[s + 1] + (uint32_t)(1 * 16 * PITCH));
                    if (m == 6)
                        LDSM4(ah[nxt][2], aB + kSw[s + 1] + (uint32_t)(2 * 16 * PITCH));
                    if (m == 8)
                        LDSM4(ah[nxt][3], aB + kSw[s + 1] + (uint32_t)(3 * 16 * PITCH));
                    if (m == 10)
                        LDSM4(bh[nxt][0], bB + kSw[s + 1] + (uint32_t)(0 * 16 * PITCH));
                    if (m == 12)
                        LDSM4(bh[nxt][1], bB + kSw[s + 1] + (uint32_t)(1 * 16 * PITCH));
                }
            }
        }
    }

    #pragma unroll
    for (int i = 0; i < 4; i++) {
        const int row = bm + wm * 64 + i * 16 + (lane >> 2);
        #pragma unroll
        for (int j = 0; j < 4; j++) {
            const int col = bn + wn * 32 + j * 8 + (lane & 3) * 2;
            __half2 h0 = __floats2half2_rn(acc[i][j][0], acc[i][j][1]);
            __half2 h1 = __floats2half2_rn(acc[i][j][2], acc[i][j][3]);
            *(__half2*)(Ch + (size_t)row * N + col)       = h0;
            *(__half2*)(Ch + (size_t)(row + 8) * N + col) = h1;
        }
    }
}

// ---------------------------------------------------------------------------
// Merged fp32 -> fp16 conversion: x, Wqkv, Wout in one grid-stride launch.
// ---------------------------------------------------------------------------
#define N4_X  (NTOK * CDIM / 4)
#define N4_W1 (C3 * CDIM / 4)
#define N4_W2 (CDIM * CDIM / 4)

__global__ __launch_bounds__(256) void cvt_all_kernel(
    const float* __restrict__ x,  __half* __restrict__ xh,
    const float* __restrict__ w1, __half* __restrict__ w1h,
    const float* __restrict__ w2, __half* __restrict__ w2h)
{
    const int total = N4_X + N4_W1 + N4_W2;
    for (int i = blockIdx.x * blockDim.x + threadIdx.x; i < total;
         i += gridDim.x * blockDim.x) {
        const float4* s;
        __half* d;
        int k;
        if (i < N4_X)              { s = (const float4*)x;  d = xh;  k = i; }
        else if (i < N4_X + N4_W1) { s = (const float4*)w1; d = w1h; k = i - N4_X; }
        else                       { s = (const float4*)w2; d = w2h; k = i - N4_X - N4_W1; }
        const float4 v = s[k];
        __half2 h0 = __floats2half2_rn(v.x, v.y);
        __half2 h1 = __floats2half2_rn(v.z, v.w);
        uint2 r;
        r.x = *(uint32_t*)&h0;
        r.y = *(uint32_t*)&h1;
        *(uint2*)(d + (size_t)k * 4) = r;
    }
}

// ---------------------------------------------------------------------------
// Attention over heads — fp16 smem, chunk-rotation swizzle, head-interleaved.
// 8 tokens/CTA, 128 threads (16/token). Thread (I,J) computes
// S[4r+I][4c+J], r,c in 0..3 (heads interleaved -> row stride 1 across I/J
// -> conflict-free 16B score loads under chunk' = (chunk + row) & 7).
// smem/token: 48 rows x 128B (q rows 0-15, k 16-31, v 32-47) + fp32 P
// (16x17) = 7232 B; token pitch 7232 = 64 mod 128 -> token pair 4 chunks
// apart. 8 tokens = 57856 B -> 3 CTAs/SM.
// ---------------------------------------------------------------------------
#define TOKB      7232
#define P_OFF_B   6144
#define ATTN_SMEM (8 * TOKB)     // 57856 B

__device__ __forceinline__ void u4_to_f8(uint4 u, float* f) {
    const __half2* hp = (const __half2*)&u;
    #pragma unroll
    for (int q = 0; q < 4; q++) {
        const float2 t = __half22float2(hp[q]);
        f[2 * q]     = t.x;
        f[2 * q + 1] = t.y;
    }
}

__global__ __launch_bounds__(128) void attn_kernel(
    const __half* __restrict__ qkv, __half* __restrict__ y)
{
    extern __shared__ char shb[];
    const int tid = threadIdx.x;
    const int tokBlk = blockIdx.x * 8;

    // ---- load: 8 tokens x 384 uint4 units; re-layout with rotation swizzle ----
    // global unit u within token: head = u/24, part = (u/8)%3, chunk = u&7
    // smem row = part*16 + head; chunk' = (chunk + row) & 7
    const uint4* src = (const uint4*)(qkv + (size_t)tokBlk * C3);
    #pragma unroll
    for (int it = 0; it < 24; it++) {
        const int i    = it * 128 + tid;
        const int t    = i / 384;
        const int u    = i % 384;
        const int head = u / 24;
        const int part = (u >> 3) % 3;
        const int c    = u & 7;
        const int row  = part * 16 + head;
        *(uint4*)(shb + t * TOKB + row * 128 + (((c + row) & 7) << 4)) = src[i];
    }
    __syncthreads();

    const int tok = tid >> 4;
    const int j   = tid & 15;
    const int I   = j >> 2;
    const int J   = j & 3;
    char* tb = shb + tok * TOKB;

    // ---- scores: S[4r+I][4c+J] = q_{4r+I} . k_{4c+J} ----
    float s[4][4];
    #pragma unroll
    for (int r = 0; r < 4; r++)
        #pragma unroll
        for (int c = 0; c < 4; c++) s[r][c] = 0.0f;

    #pragma unroll
    for (int dd = 0; dd < 8; dd++) {
        float qf[4][8], kf[4][8];
        #pragma unroll
        for (int r = 0; r < 4; r++) {
            const int row = 4 * r + I;                    // q rows 0..15
            uint4 u = *(const uint4*)(tb + row * 128 + (((dd + row) & 7) << 4));
            u4_to_f8(u, qf[r]);
        }
        #pragma unroll
        for (int c = 0; c < 4; c++) {
            const int row = 16 + 4 * c + J;               // k rows 16..31
            uint4 u = *(const uint4*)(tb + row * 128 + (((dd + row) & 7) << 4));
            u4_to_f8(u, kf[c]);
        }
        #pragma unroll
        for (int r = 0; r < 4; r++)
            #pragma unroll
            for (int c = 0; c < 4; c++) {
                #pragma unroll
                for (int e = 0; e < 8; e++)
                    s[r][c] += qf[r][e] * kf[c][e];
            }
    }

    // ---- softmax over g = 4c+J (16 values span 4 J-threads) ----
    float den[4];
    #pragma unroll
    for (int r = 0; r < 4; r++) {
        float mx = fmaxf(fmaxf(s[r][0], s[r][1]), fmaxf(s[r][2], s[r][3]));
        mx = fmaxf(mx, __shfl_xor_sync(0xFFFFFFFFu, mx, 1));
        mx = fmaxf(mx, __shfl_xor_sync(0xFFFFFFFFu, mx, 2));
        float sum = 0.0f;
        #pragma unroll
        for (int c = 0; c < 4; c++) {
            s[r][c] = __expf((s[r][c] - mx) * 0.125f);
            sum += s[r][c];
        }
        sum += __shfl_xor_sync(0xFFFFFFFFu, sum, 1);
        sum += __shfl_xor_sync(0xFFFFFFFFu, sum, 2);
        den[r] = 1.0f / sum;
    }

    // ---- P (unnormalized exp, fp32) ----
    float* P = (float*)(tb + P_OFF_B);
    #pragma unroll
    for (int r = 0; r < 4; r++)
        #pragma unroll
        for (int c = 0; c < 4; c++)
            P[(4 * r + I) * 17 + (4 * c + J)] = s[r][c];
    __syncwarp();

    // ---- out: O[4r+I][16J+e] = sum_g P[4r+I][g] * v[g][16J+e] ----
    float o[4][16];
    #pragma unroll
    for (int r = 0; r < 4; r++)
        #pragma unroll
        for (int e = 0; e < 16; e++) o[r][e] = 0.0f;

    #pragma unroll
    for (int g = 0; g < 16; g++) {
        float a[4];
        #pragma unroll
        for (int r = 0; r < 4; r++) a[r] = P[(4 * r + I) * 17 + g];
        const int row = 32 + g;                           // v rows 32..47
        float vf[16];
        uint4 u0 = *(const uint4*)(tb + row * 128 + ((((2 * J)     + row) & 7) << 4));
        uint4 u1 = *(const uint4*)(tb + row * 128 + ((((2 * J + 1) + row) & 7) << 4));
        u4_to_f8(u0, vf);
        u4_to_f8(u1, vf + 8);
        #pragma unroll
        for (int r = 0; r < 4; r++)
            #pragma unroll
            for (int e = 0; e < 16; e++)
                o[r][e] += a[r] * vf[e];
    }

    // ---- store y (fp16): rows are heads 4r+I ----
    __half* yt = y + (size_t)(tokBlk + tok) * CDIM;
    #pragma unroll
    for (int r = 0; r < 4; r++) {
        const int h = 4 * r + I;
        #pragma unroll
        for (int qq = 0; qq < 2; qq++) {
            __half2 p0 = __floats2half2_rn(o[r][qq*8+0] * den[r], o[r][qq*8+1] * den[r]);
            __half2 p1 = __floats2half2_rn(o[r][qq*8+2] * den[r], o[r][qq*8+3] * den[r]);
            __half2 p2 = __floats2half2_rn(o[r][qq*8+4] * den[r], o[r][qq*8+5] * den[r]);
            __half2 p3 = __floats2half2_rn(o[r][qq*8+6] * den[r], o[r][qq*8+7] * den[r]);
            uint4 w;
            w.x = *(uint32_t*)&p0; w.y = *(uint32_t*)&p1;
            w.z = *(uint32_t*)&p2; w.w = *(uint32_t*)&p3;
            *(uint4*)(yt + h * 64 + 16 * J + qq * 8) = w;
        }
    }
}

// ---------------------------------------------------------------------------
extern "C" void kernel_launch(void* const* d_in, const int* in_sizes, int n_in,
                              void* d_out, int out_size)
{
    const float* x    = (const float*)d_in[0];
    const float* Wqkv = (const float*)d_in[1];
    const float* Wout = (const float*)d_in[2];
    const float* bout = (const float*)d_in[3];
    float* out = (float*)d_out;

    __half *qkvh, *yh, *xh, *w1h, *w2h;
    cudaGetSymbolAddress((void**)&qkvh, g_qkvh);
    cudaGetSymbolAddress((void**)&yh,   g_yh);
    cudaGetSymbolAddress((void**)&xh,   g_xh);
    cudaGetSymbolAddress((void**)&w1h,  g_w1h);
    cudaGetSymbolAddress((void**)&w2h,  g_w2h);

    cudaFuncSetAttribute(f16_gemm<false>, cudaFuncAttributeMaxDynamicSharedMemorySize, SMEM_B);
    cudaFuncSetAttribute(f16_gemm_wide,   cudaFuncAttributeMaxDynamicSharedMemorySize, SMEM_W);
    cudaFuncSetAttribute(attn_kernel,     cudaFuncAttributeMaxDynamicSharedMemorySize, ATTN_SMEM);

    // merged fp16 conversion (x, Wqkv, Wout)
    cvt_all_kernel<<<2960, 256>>>(x, xh, Wqkv, w1h, Wout, w2h);

    // GEMM1: qkvh = xh @ w1h^T   (16384 x 3072, K=1024), 128x256 tiles, fp16 out
    f16_gemm_wide<<<dim3(C3 / 256, NTOK / 128), 512, SMEM_W>>>(
        xh, w1h, qkvh, NTOK, C3);

    // attention over heads (fp16 in/out, fp16 smem)
    attn_kernel<<<NTOK / 8, 128, ATTN_SMEM>>>(qkvh, yh);

    // GEMM2: out = yh @ w2h^T + bout   (16384 x 1024, K=1024), 128x128 tiles
    f16_gemm<false><<<dim3(CDIM / 128, NTOK / 128), 256, SMEM_B>>>(
        yh, w2h, bout, out, nullptr, NTOK, CDIM);
}